// round 1
// baseline (speedup 1.0000x reference)
#include <cuda_runtime.h>
#include <math.h>

#define D_MODEL 1024
#define SEQ     2048
#define BATCH   2
#define NHEAD   16
#define DH      64
#define D3      (3 * D_MODEL)

// Scratch (no cudaMalloc allowed): qkv [B,S,3D] and attention output [B,S,D]
__device__ float g_qkv[BATCH * SEQ * D3];      // ~50 MB
__device__ float g_attn[BATCH * SEQ * D_MODEL]; // ~17 MB

#define NEG_INF __int_as_float(0xff800000)

// ---------------------------------------------------------------------------
// Classic 128x128x8 SGEMM, row-major A[M,K] * B[K,N] -> C[M,N]
// 256 threads, 8x8 micro-tile per thread, float4 smem access.
// M % 128 == 0, N % 128 == 0, K % 8 == 0 (always true here).
// ---------------------------------------------------------------------------
__global__ __launch_bounds__(256) void sgemm_kernel(
    const float* __restrict__ A, const float* __restrict__ B,
    float* __restrict__ C, int M, int N, int K)
{
    constexpr int BM = 128, BN = 128, BK = 8, TM = 8, TN = 8;
    __shared__ float As[BK][BM];
    __shared__ float Bs[BK][BN];

    const int tid  = threadIdx.x;
    const int cRow = blockIdx.y * BM;
    const int cCol = blockIdx.x * BN;

    // A tile loader: 128 rows x 8 cols = 256 float4
    const int aRow = tid >> 1;            // 0..127
    const int aCol = (tid & 1) * 4;       // 0 or 4
    // B tile loader: 8 rows x 128 cols = 256 float4
    const int bRow = tid >> 5;            // 0..7
    const int bCol = (tid & 31) * 4;      // 0..124

    const int ty = (tid >> 4) * TM;       // 0..120
    const int tx = (tid & 15) * TN;       // 0..120

    float acc[TM][TN];
#pragma unroll
    for (int i = 0; i < TM; i++)
#pragma unroll
        for (int j = 0; j < TN; j++) acc[i][j] = 0.f;

    const float* Aptr = A + (cRow + aRow) * K + aCol;
    const float* Bptr = B + bRow * N + cCol + bCol;

    for (int k0 = 0; k0 < K; k0 += BK) {
        float4 av = *reinterpret_cast<const float4*>(Aptr + k0);
        float4 bv = *reinterpret_cast<const float4*>(Bptr + (size_t)k0 * N);
        As[aCol + 0][aRow] = av.x;
        As[aCol + 1][aRow] = av.y;
        As[aCol + 2][aRow] = av.z;
        As[aCol + 3][aRow] = av.w;
        *reinterpret_cast<float4*>(&Bs[bRow][bCol]) = bv;
        __syncthreads();

#pragma unroll
        for (int k = 0; k < BK; k++) {
            float4 a0 = *reinterpret_cast<const float4*>(&As[k][ty]);
            float4 a1 = *reinterpret_cast<const float4*>(&As[k][ty + 4]);
            float4 b0 = *reinterpret_cast<const float4*>(&Bs[k][tx]);
            float4 b1 = *reinterpret_cast<const float4*>(&Bs[k][tx + 4]);
            float ra[TM] = {a0.x, a0.y, a0.z, a0.w, a1.x, a1.y, a1.z, a1.w};
            float rb[TN] = {b0.x, b0.y, b0.z, b0.w, b1.x, b1.y, b1.z, b1.w};
#pragma unroll
            for (int i = 0; i < TM; i++)
#pragma unroll
                for (int j = 0; j < TN; j++)
                    acc[i][j] += ra[i] * rb[j];
        }
        __syncthreads();
    }

#pragma unroll
    for (int i = 0; i < TM; i++) {
        float* crow = C + (size_t)(cRow + ty + i) * N + cCol + tx;
        float4 v0 = make_float4(acc[i][0], acc[i][1], acc[i][2], acc[i][3]);
        float4 v1 = make_float4(acc[i][4], acc[i][5], acc[i][6], acc[i][7]);
        *reinterpret_cast<float4*>(crow)     = v0;
        *reinterpret_cast<float4*>(crow + 4) = v1;
    }
}

// ---------------------------------------------------------------------------
// Flash-style causal attention. One block = (64 q rows, 1 head, 1 batch).
// 64 threads, thread t owns q-row t of the tile. Online softmax in registers,
// K/V 64x64 tiles staged in smem, read via broadcast LDS.128.
// ---------------------------------------------------------------------------
__global__ __launch_bounds__(64) void attn_kernel(
    const float* __restrict__ qkv, float* __restrict__ attn_out)
{
    const int qb = blockIdx.x;   // 0..31  q tile
    const int h  = blockIdx.y;   // 0..15
    const int b  = blockIdx.z;   // 0..1
    const int t  = threadIdx.x;  // 0..63

    __shared__ float Ksh[64][64];
    __shared__ float Vsh[64][64];

    const int qi = qb * 64 + t;
    const float* qrow = qkv + (size_t)(b * SEQ + qi) * D3 + h * DH;

    float q[DH];
#pragma unroll
    for (int d = 0; d < DH; d += 4) {
        float4 v = *reinterpret_cast<const float4*>(qrow + d);
        q[d] = v.x; q[d + 1] = v.y; q[d + 2] = v.z; q[d + 3] = v.w;
    }

    float o[DH];
#pragma unroll
    for (int d = 0; d < DH; d++) o[d] = 0.f;
    float m = NEG_INF;
    float l = 0.f;

    // cooperative tile-load mapping: 4 rows per pass, 16 threads per row
    const int r4 = t >> 4;          // 0..3
    const int c4 = (t & 15) * 4;    // 0..60
    const size_t base = (size_t)(b * SEQ) * D3 + h * DH;

    for (int kt = 0; kt <= qb; kt++) {
#pragma unroll
        for (int p = 0; p < 16; p++) {
            int row = p * 4 + r4;
            size_t g = base + (size_t)(kt * 64 + row) * D3 + c4;
            *reinterpret_cast<float4*>(&Ksh[row][c4]) =
                *reinterpret_cast<const float4*>(qkv + g + D_MODEL);
            *reinterpret_cast<float4*>(&Vsh[row][c4]) =
                *reinterpret_cast<const float4*>(qkv + g + 2 * D_MODEL);
        }
        __syncthreads();

        // scores: s[j] = q . K[j]
        float s[64];
#pragma unroll
        for (int j = 0; j < 64; j += 4) {
            float s0 = 0.f, s1 = 0.f, s2 = 0.f, s3 = 0.f;
#pragma unroll
            for (int d = 0; d < DH; d += 4) {
                float4 k0 = *reinterpret_cast<const float4*>(&Ksh[j][d]);
                float4 k1 = *reinterpret_cast<const float4*>(&Ksh[j + 1][d]);
                float4 k2 = *reinterpret_cast<const float4*>(&Ksh[j + 2][d]);
                float4 k3 = *reinterpret_cast<const float4*>(&Ksh[j + 3][d]);
                s0 += q[d] * k0.x + q[d+1] * k0.y + q[d+2] * k0.z + q[d+3] * k0.w;
                s1 += q[d] * k1.x + q[d+1] * k1.y + q[d+2] * k1.z + q[d+3] * k1.w;
                s2 += q[d] * k2.x + q[d+1] * k2.y + q[d+2] * k2.z + q[d+3] * k2.w;
                s3 += q[d] * k3.x + q[d+1] * k3.y + q[d+2] * k3.z + q[d+3] * k3.w;
            }
            s[j] = s0; s[j + 1] = s1; s[j + 2] = s2; s[j + 3] = s3;
        }

        const bool diag = (kt == qb);
        float mt = m;
#pragma unroll
        for (int j = 0; j < 64; j++) {
            float v = s[j] * 0.125f;          // 1/sqrt(64)
            if (diag && j > t) v = NEG_INF;   // causal mask
            s[j] = v;
            mt = fmaxf(mt, v);
        }

        float corr = __expf(m - mt);
        m = mt;
        float ls = 0.f;
#pragma unroll
        for (int j = 0; j < 64; j++) {
            float p = __expf(s[j] - mt);
            s[j] = p;
            ls += p;
        }
        l = l * corr + ls;

#pragma unroll
        for (int d = 0; d < DH; d++) o[d] *= corr;
#pragma unroll
        for (int j = 0; j < 64; j++) {
            float pj = s[j];
#pragma unroll
            for (int d = 0; d < DH; d += 4) {
                float4 v = *reinterpret_cast<const float4*>(&Vsh[j][d]);
                o[d]     += pj * v.x;
                o[d + 1] += pj * v.y;
                o[d + 2] += pj * v.z;
                o[d + 3] += pj * v.w;
            }
        }
        __syncthreads();
    }

    float inv = 1.f / l;
    float* orow = attn_out + (size_t)(b * SEQ + qi) * D_MODEL + h * DH;
#pragma unroll
    for (int d = 0; d < DH; d += 4) {
        float4 v = make_float4(o[d] * inv, o[d + 1] * inv,
                               o[d + 2] * inv, o[d + 3] * inv);
        *reinterpret_cast<float4*>(orow + d) = v;
    }
}

// ---------------------------------------------------------------------------
extern "C" void kernel_launch(void* const* d_in, const int* in_sizes, int n_in,
                              void* d_out, int out_size)
{
    const float* x     = (const float*)d_in[0];  // [2,2048,1024]
    const float* W_in  = (const float*)d_in[1];  // [1024,3072]
    const float* W_out = (const float*)d_in[2];  // [1024,1024]
    float* out = (float*)d_out;                  // [2,2048,1024]

    float* qkv_buf;
    float* attn_buf;
    cudaGetSymbolAddress((void**)&qkv_buf, g_qkv);
    cudaGetSymbolAddress((void**)&attn_buf, g_attn);

    const int M = BATCH * SEQ;  // 4096

    // 1) qkv = x @ W_in   [4096,1024]x[1024,3072]
    {
        dim3 grid(D3 / 128, M / 128);
        sgemm_kernel<<<grid, 256>>>(x, W_in, qkv_buf, M, D3, D_MODEL);
    }
    // 2) causal multi-head attention
    {
        dim3 grid(SEQ / 64, NHEAD, BATCH);
        attn_kernel<<<grid, 64>>>(qkv_buf, attn_buf);
    }
    // 3) out = attn @ W_out  [4096,1024]x[1024,1024]
    {
        dim3 grid(D_MODEL / 128, M / 128);
        sgemm_kernel<<<grid, 256>>>(attn_buf, W_out, out, M, D_MODEL, D_MODEL);
    }
}

// round 2
// speedup vs baseline: 1.6267x; 1.6267x over previous
#include <cuda_runtime.h>
#include <math.h>

#define D_MODEL 1024
#define SEQ     2048
#define BATCH   2
#define NHEAD   16
#define DH      64
#define D3      (3 * D_MODEL)

__device__ float g_qkv[BATCH * SEQ * D3];       // ~50 MB scratch
__device__ float g_attn[BATCH * SEQ * D_MODEL]; // ~17 MB scratch

#define NEG_INF __int_as_float(0xff800000)

// ---------------------------------------------------------------------------
// Classic 128x128x8 SGEMM, row-major A[M,K] * B[K,N] -> C[M,N]  (unchanged R1)
// ---------------------------------------------------------------------------
__global__ __launch_bounds__(256) void sgemm_kernel(
    const float* __restrict__ A, const float* __restrict__ B,
    float* __restrict__ C, int M, int N, int K)
{
    constexpr int BM = 128, BN = 128, BK = 8, TM = 8, TN = 8;
    __shared__ float As[BK][BM];
    __shared__ float Bs[BK][BN];

    const int tid  = threadIdx.x;
    const int cRow = blockIdx.y * BM;
    const int cCol = blockIdx.x * BN;

    const int aRow = tid >> 1;
    const int aCol = (tid & 1) * 4;
    const int bRow = tid >> 5;
    const int bCol = (tid & 31) * 4;

    const int ty = (tid >> 4) * TM;
    const int tx = (tid & 15) * TN;

    float acc[TM][TN];
#pragma unroll
    for (int i = 0; i < TM; i++)
#pragma unroll
        for (int j = 0; j < TN; j++) acc[i][j] = 0.f;

    const float* Aptr = A + (cRow + aRow) * K + aCol;
    const float* Bptr = B + bRow * N + cCol + bCol;

    for (int k0 = 0; k0 < K; k0 += BK) {
        float4 av = *reinterpret_cast<const float4*>(Aptr + k0);
        float4 bv = *reinterpret_cast<const float4*>(Bptr + (size_t)k0 * N);
        As[aCol + 0][aRow] = av.x;
        As[aCol + 1][aRow] = av.y;
        As[aCol + 2][aRow] = av.z;
        As[aCol + 3][aRow] = av.w;
        *reinterpret_cast<float4*>(&Bs[bRow][bCol]) = bv;
        __syncthreads();

#pragma unroll
        for (int k = 0; k < BK; k++) {
            float4 a0 = *reinterpret_cast<const float4*>(&As[k][ty]);
            float4 a1 = *reinterpret_cast<const float4*>(&As[k][ty + 4]);
            float4 b0 = *reinterpret_cast<const float4*>(&Bs[k][tx]);
            float4 b1 = *reinterpret_cast<const float4*>(&Bs[k][tx + 4]);
            float ra[TM] = {a0.x, a0.y, a0.z, a0.w, a1.x, a1.y, a1.z, a1.w};
            float rb[TN] = {b0.x, b0.y, b0.z, b0.w, b1.x, b1.y, b1.z, b1.w};
#pragma unroll
            for (int i = 0; i < TM; i++)
#pragma unroll
                for (int j = 0; j < TN; j++)
                    acc[i][j] += ra[i] * rb[j];
        }
        __syncthreads();
    }

#pragma unroll
    for (int i = 0; i < TM; i++) {
        float* crow = C + (size_t)(cRow + ty + i) * N + cCol + tx;
        *reinterpret_cast<float4*>(crow)     = make_float4(acc[i][0], acc[i][1], acc[i][2], acc[i][3]);
        *reinterpret_cast<float4*>(crow + 4) = make_float4(acc[i][4], acc[i][5], acc[i][6], acc[i][7]);
    }
}

// ---------------------------------------------------------------------------
// Flash attention, GEMM-style. Block = (64 q-rows, head, batch), 256 threads.
// Each thread owns a 4x4 tile of S and of O (16x16 thread grid).
// Qt, Kt transposed in smem [d][row]; Vs, Pt swizzled; P aliases K's buffer.
// Online softmax per q-row reduced with shfl_xor across the 16-lane groups.
// ---------------------------------------------------------------------------
__global__ __launch_bounds__(256) void attn_kernel(
    const float* __restrict__ qkv, float* __restrict__ attn_out)
{
    __shared__ float Qt[64 * 64];   // Qt[d][i]
    __shared__ float KPt[64 * 64];  // Kt[d][j], later Pt[j][i] (swizzled)
    __shared__ float Vs[64 * 64];   // Vs[k][d]  (swizzled)

    const int qb = blockIdx.x;   // q tile 0..31
    const int h  = blockIdx.y;
    const int b  = blockIdx.z;
    const int tid = threadIdx.x;

    const int ty = (tid >> 4) * 4;   // q-row group   0..60
    const int tx = (tid & 15) * 4;   // col group     0..60
    const int li = tid & 63;         // loader row
    const int q4 = tid >> 6;         // loader d-quarter

    const size_t base = (size_t)(b * SEQ) * D3 + h * DH;

    // Load Q tile transposed: Qt[d][i]
    {
        const float* qr = qkv + base + (size_t)(qb * 64 + li) * D3 + q4 * 16;
#pragma unroll
        for (int c = 0; c < 4; c++) {
            float4 v = *reinterpret_cast<const float4*>(qr + c * 4);
            int d = q4 * 16 + c * 4;
            Qt[(d + 0) * 64 + li] = v.x;
            Qt[(d + 1) * 64 + li] = v.y;
            Qt[(d + 2) * 64 + li] = v.z;
            Qt[(d + 3) * 64 + li] = v.w;
        }
    }

    float O[4][4];
    float m[4], l[4];
#pragma unroll
    for (int i = 0; i < 4; i++) {
        m[i] = NEG_INF; l[i] = 0.f;
#pragma unroll
        for (int j = 0; j < 4; j++) O[i][j] = 0.f;
    }

    for (int kt = 0; kt <= qb; kt++) {
        __syncthreads();  // prev iteration done reading KPt/Vs

        // Load K transposed, V swizzled
        {
            const float* kr = qkv + base + (size_t)(kt * 64 + li) * D3 + D_MODEL + q4 * 16;
#pragma unroll
            for (int c = 0; c < 4; c++) {
                int d = q4 * 16 + c * 4;
                float4 kv = *reinterpret_cast<const float4*>(kr + c * 4);
                KPt[(d + 0) * 64 + li] = kv.x;
                KPt[(d + 1) * 64 + li] = kv.y;
                KPt[(d + 2) * 64 + li] = kv.z;
                KPt[(d + 3) * 64 + li] = kv.w;
                float4 vv = *reinterpret_cast<const float4*>(kr + D_MODEL + c * 4);
                int pc = (d >> 2) ^ (li & 15);
                *reinterpret_cast<float4*>(&Vs[li * 64 + pc * 4]) = vv;
            }
        }
        __syncthreads();

        // S = Q . K^T (64x64x64)
        float s[4][4];
#pragma unroll
        for (int i = 0; i < 4; i++)
#pragma unroll
            for (int j = 0; j < 4; j++) s[i][j] = 0.f;

#pragma unroll 8
        for (int d = 0; d < 64; d++) {
            float4 av = *reinterpret_cast<const float4*>(&Qt[d * 64 + ty]);
            float4 bv = *reinterpret_cast<const float4*>(&KPt[d * 64 + tx]);
            float ra[4] = {av.x, av.y, av.z, av.w};
            float rb[4] = {bv.x, bv.y, bv.z, bv.w};
#pragma unroll
            for (int i = 0; i < 4; i++)
#pragma unroll
                for (int j = 0; j < 4; j++)
                    s[i][j] += ra[i] * rb[j];
        }

        // online softmax
        const bool diag = (kt == qb);
        float corr[4];
#pragma unroll
        for (int i = 0; i < 4; i++) {
#pragma unroll
            for (int j = 0; j < 4; j++) {
                float v = s[i][j] * 0.125f;                 // 1/sqrt(64)
                if (diag && (tx + j) > (ty + i)) v = NEG_INF;
                s[i][j] = v;
            }
            float mm = fmaxf(fmaxf(s[i][0], s[i][1]), fmaxf(s[i][2], s[i][3]));
            mm = fmaxf(mm, __shfl_xor_sync(0xffffffffu, mm, 1));
            mm = fmaxf(mm, __shfl_xor_sync(0xffffffffu, mm, 2));
            mm = fmaxf(mm, __shfl_xor_sync(0xffffffffu, mm, 4));
            mm = fmaxf(mm, __shfl_xor_sync(0xffffffffu, mm, 8));
            float nm = fmaxf(mm, m[i]);
            corr[i] = __expf(m[i] - nm);
            m[i] = nm;
            float ps = 0.f;
#pragma unroll
            for (int j = 0; j < 4; j++) {
                float p = __expf(s[i][j] - nm);
                s[i][j] = p;
                ps += p;
            }
            ps += __shfl_xor_sync(0xffffffffu, ps, 1);
            ps += __shfl_xor_sync(0xffffffffu, ps, 2);
            ps += __shfl_xor_sync(0xffffffffu, ps, 4);
            ps += __shfl_xor_sync(0xffffffffu, ps, 8);
            l[i] = l[i] * corr[i] + ps;
#pragma unroll
            for (int j = 0; j < 4; j++) O[i][j] *= corr[i];
        }

        __syncthreads();  // everyone done reading Kt

        // write P transposed+swizzled into KPt: Pt[j][i]
#pragma unroll
        for (int j = 0; j < 4; j++) {
            int row = tx + j;
            int pc = (ty >> 2) ^ (row & 15);
            *reinterpret_cast<float4*>(&KPt[row * 64 + pc * 4]) =
                make_float4(s[0][j], s[1][j], s[2][j], s[3][j]);
        }
        __syncthreads();

        // O += P . V  (64x64x64)
#pragma unroll 8
        for (int k = 0; k < 64; k++) {
            int pa = (ty >> 2) ^ (k & 15);
            float4 av = *reinterpret_cast<const float4*>(&KPt[k * 64 + pa * 4]);
            int pb = (tx >> 2) ^ (k & 15);
            float4 bv = *reinterpret_cast<const float4*>(&Vs[k * 64 + pb * 4]);
            float ra[4] = {av.x, av.y, av.z, av.w};
            float rb[4] = {bv.x, bv.y, bv.z, bv.w};
#pragma unroll
            for (int i = 0; i < 4; i++)
#pragma unroll
                for (int j = 0; j < 4; j++)
                    O[i][j] += ra[i] * rb[j];
        }
    }

    // epilogue: O / l  -> attn_out[b, qb*64+ty+i, h*64+tx..]
#pragma unroll
    for (int i = 0; i < 4; i++) {
        float inv = 1.f / l[i];
        float* orow = attn_out + (size_t)(b * SEQ + qb * 64 + ty + i) * D_MODEL + h * DH + tx;
        *reinterpret_cast<float4*>(orow) =
            make_float4(O[i][0] * inv, O[i][1] * inv, O[i][2] * inv, O[i][3] * inv);
    }
}

// ---------------------------------------------------------------------------
extern "C" void kernel_launch(void* const* d_in, const int* in_sizes, int n_in,
                              void* d_out, int out_size)
{
    const float* x     = (const float*)d_in[0];
    const float* W_in  = (const float*)d_in[1];
    const float* W_out = (const float*)d_in[2];
    float* out = (float*)d_out;

    float* qkv_buf;
    float* attn_buf;
    cudaGetSymbolAddress((void**)&qkv_buf, g_qkv);
    cudaGetSymbolAddress((void**)&attn_buf, g_attn);

    const int M = BATCH * SEQ;  // 4096

    {   // qkv = x @ W_in
        dim3 grid(D3 / 128, M / 128);
        sgemm_kernel<<<grid, 256>>>(x, W_in, qkv_buf, M, D3, D_MODEL);
    }
    {   // causal MHA
        dim3 grid(SEQ / 64, NHEAD, BATCH);
        attn_kernel<<<grid, 256>>>(qkv_buf, attn_buf);
    }
    {   // out = attn @ W_out
        dim3 grid(D_MODEL / 128, M / 128);
        sgemm_kernel<<<grid, 256>>>(attn_buf, W_out, out, M, D_MODEL, D_MODEL);
    }
}